// round 16
// baseline (speedup 1.0000x reference)
#include <cuda_runtime.h>
#include <cstdint>

// dynFilter: out[b,1,h,w] = tanh( sum_{c,ky,kx} x[b,c,h+ky-2,w+kx-2] * filt[b, c*25+ky*5+kx, h, w] )
// x [8,4,256,256] f32, filt [8,100,256,256] f32, out [8,1,256,256] f32.
// R15 (bulk-async, DQ=2, producer-inside-consumer) failed: refill gated on all
// 128 consumer arrivals -> serialized, DRAM 60%.
// R16: warp-specialized producer (160-thr CTA: 4 consumer warps + 1 producer
// warp), DQ=3 ring of 10KB group-stages, dynamic smem 56KB -> 4 CTAs/SM,
// 512 CTAs x 2 tiles (ring never drains). Producer runs 3 groups (~30KB)
// ahead per CTA => ~120KB in flight per SM, fully decoupled from registers.

#define KK 5
#define PADK 2
#define CC 4
#define HH 256
#define WW 256
#define TILE_H 2
#define NROWS (TILE_H + 2 * PADK)       // 6 halo rows
#define NCOLS (WW + 2 * PADK)           // 260 used cols
#define NCOLS_PAD 264
#define DQ 3                            // ring stages
#define NGT (CC * KK)                   // 20 groups per tile
#define NTILES_PER_CTA 2
#define NGTOT (NGT * NTILES_PER_CTA)    // 40 groups per CTA
#define PLANE_BYTES (TILE_H * WW * 4)   // 2048
#define STAGE_BYTES (KK * PLANE_BYTES)  // 10240

#define XS_BYTES   (CC * NROWS * NCOLS_PAD * 4)      // 25344
#define RING_BYTES (DQ * KK * TILE_H * WW * 4)       // 30720
#define MB_OFF     (XS_BYTES + RING_BYTES)           // 56064
#define SMEM_BYTES (MB_OFF + 2 * DQ * 8)             // 56112

__device__ __forceinline__ float tanh_approx(float v) {
    float r;
    asm("tanh.approx.f32 %0, %1;" : "=f"(r) : "f"(v));
    return r;
}
__device__ __forceinline__ uint32_t smem_u32(const void* p) {
    return (uint32_t)__cvta_generic_to_shared(p);
}
__device__ __forceinline__ void mbar_init(uint32_t a, uint32_t cnt) {
    asm volatile("mbarrier.init.shared.b64 [%0], %1;" :: "r"(a), "r"(cnt) : "memory");
}
__device__ __forceinline__ void mbar_expect_tx(uint32_t a, uint32_t bytes) {
    asm volatile("mbarrier.arrive.expect_tx.shared.b64 _, [%0], %1;" :: "r"(a), "r"(bytes) : "memory");
}
__device__ __forceinline__ void mbar_arrive(uint32_t a) {
    asm volatile("mbarrier.arrive.shared.b64 _, [%0];" :: "r"(a) : "memory");
}
__device__ __forceinline__ void mbar_wait(uint32_t a, uint32_t parity) {
    uint32_t done;
    asm volatile(
        "{\n\t.reg .pred p;\n\t"
        "mbarrier.try_wait.parity.acquire.cta.shared::cta.b64 p, [%1], %2;\n\t"
        "selp.b32 %0, 1, 0, p;\n\t}"
        : "=r"(done) : "r"(a), "r"(parity) : "memory");
    if (!done) {
        asm volatile(
            "{\n\t.reg .pred P1;\n\t"
            "W_%=:\n\t"
            "mbarrier.try_wait.parity.acquire.cta.shared::cta.b64 P1, [%0], %1, 0x989680;\n\t"
            "@P1 bra.uni D_%=;\n\t"
            "bra.uni W_%=;\n\t"
            "D_%=:\n\t}"
            :: "r"(a), "r"(parity) : "memory");
    }
}
__device__ __forceinline__ void bulk_g2s(uint32_t dst, const void* src,
                                         uint32_t bytes, uint32_t mbar) {
    asm volatile(
        "cp.async.bulk.shared::cluster.global.mbarrier::complete_tx::bytes "
        "[%0], [%1], %2, [%3];"
        :: "r"(dst), "l"(src), "r"(bytes), "r"(mbar) : "memory");
}

__global__ __launch_bounds__(160, 4)
void dynfilter_kernel(const float* __restrict__ x,
                      const float* __restrict__ filt,
                      float* __restrict__ out)
{
    extern __shared__ __align__(16) char smem[];
    float (*xs)[NROWS][NCOLS_PAD] = (float (*)[NROWS][NCOLS_PAD])smem;
    float* ring = (float*)(smem + XS_BYTES);          // [DQ][KK][TILE_H*WW]
    const uint32_t ringb = smem_u32(ring);
    const uint32_t fullb = smem_u32(smem + MB_OFF);
    const uint32_t empb  = smem_u32(smem + MB_OFF + DQ * 8);

    const int tid = threadIdx.x;
    const int t0  = blockIdx.x * NTILES_PER_CTA;

    if (tid == 0) {
        #pragma unroll
        for (int s = 0; s < DQ; ++s) {
            mbar_init(fullb + 8u * s, 1);    // producer's expect_tx arrive
            mbar_init(empb  + 8u * s, 128);  // 128 consumer arrivals
        }
        asm volatile("fence.proxy.async.shared::cta;" ::: "memory");
    }
    __syncthreads();   // all 160 threads

    if (tid >= 128) {
        // ---------------- Producer warp (warp 4) ----------------
        if (tid == 128) {
            for (int g = 0; g < NGTOT; ++g) {
                const int slot = g % DQ;
                const int r    = g / DQ;
                if (r > 0) mbar_wait(empb + 8u * slot, (uint32_t)((r - 1) & 1));

                const int tile = t0 + g / NGT;
                const int gl   = g % NGT;
                const int b    = tile >> 7;
                const int h0   = (tile & 127) * TILE_H;
                const float* fb =
                    filt + (((long)b * (CC * KK * KK)) * HH + h0) * WW;

                mbar_expect_tx(fullb + 8u * slot, STAGE_BYTES);
                #pragma unroll
                for (int kx = 0; kx < KK; ++kx) {
                    const uint32_t dst =
                        ringb + (uint32_t)(slot * KK + kx) * PLANE_BYTES;
                    bulk_g2s(dst, fb + (long)(gl * KK + kx) * (HH * WW),
                             PLANE_BYTES, fullb + 8u * slot);
                }
            }
        }
    } else {
        // ---------------- Consumer warps (0-3) ----------------
        const int hr = tid >> 6;        // 0..1 output row
        const int q  = tid & 63;        // float4 column
        const int w  = q << 2;

        #pragma unroll 1
        for (int tt = 0; tt < NTILES_PER_CTA; ++tt) {
            const int tile = t0 + tt;
            const int b    = tile >> 7;
            const int h0   = (tile & 127) * TILE_H;

            // consumer-only barrier: protect xs from overwrite while in use
            if (tt) asm volatile("bar.sync 1, 128;" ::: "memory");
            for (int idx = tid; idx < CC * NROWS * NCOLS; idx += 128) {
                const int c   = idx / (NROWS * NCOLS);
                const int rem = idx % (NROWS * NCOLS);
                const int rr  = rem / NCOLS;
                const int cx  = rem % NCOLS;
                const int gr  = h0 - PADK + rr;
                const int gc  = cx - PADK;
                float v = 0.0f;
                if (gr >= 0 && gr < HH && gc >= 0 && gc < WW)
                    v = __ldg(&x[(((b * CC) + c) * HH + gr) * WW + gc]);
                xs[c][rr][cx] = v;
            }
            asm volatile("bar.sync 1, 128;" ::: "memory");

            float acc0 = 0.f, acc1 = 0.f, acc2 = 0.f, acc3 = 0.f;

            #pragma unroll
            for (int gl = 0; gl < NGT; ++gl) {
                const int g     = tt * NGT + gl;
                const int slot  = g % DQ;
                const uint32_t phase = (uint32_t)((g / DQ) & 1);
                const int c  = gl / KK;
                const int ky = gl % KK;

                mbar_wait(fullb + 8u * slot, phase);

                const float4 a  = *(const float4*)&xs[c][hr + ky][w];
                const float4 bb = *(const float4*)&xs[c][hr + ky][w + 4];
                const float x0 = a.x,  x1 = a.y,  x2 = a.z,  x3 = a.w;
                const float x4 = bb.x, x5 = bb.y, x6 = bb.z, x7 = bb.w;
                const float wv[8] = {x0, x1, x2, x3, x4, x5, x6, x7};

                const float* rs = ring + (slot * KK) * (TILE_H * WW) + hr * WW + w;
                #pragma unroll
                for (int kx = 0; kx < KK; ++kx) {
                    const float4 f = *(const float4*)(rs + kx * (TILE_H * WW));
                    acc0 = fmaf(wv[kx + 0], f.x, acc0);
                    acc1 = fmaf(wv[kx + 1], f.y, acc1);
                    acc2 = fmaf(wv[kx + 2], f.z, acc2);
                    acc3 = fmaf(wv[kx + 3], f.w, acc3);
                }
                mbar_arrive(empb + 8u * slot);
            }

            float4 o;
            o.x = tanh_approx(acc0);
            o.y = tanh_approx(acc1);
            o.z = tanh_approx(acc2);
            o.w = tanh_approx(acc3);
            ((float4*)out)[((long)b * HH + (h0 + hr)) * (WW / 4) + q] = o;
        }
    }
}

extern "C" void kernel_launch(void* const* d_in, const int* in_sizes, int n_in,
                              void* d_out, int out_size)
{
    const float* x    = (const float*)d_in[0];   // [8,4,256,256]
    const float* filt = (const float*)d_in[1];   // [8,100,256,256]
    float* out        = (float*)d_out;           // [8,1,256,256]

    cudaFuncSetAttribute(dynfilter_kernel,
                         cudaFuncAttributeMaxDynamicSharedMemorySize,
                         SMEM_BYTES);
    dim3 grid(512);      // 512 CTAs x 2 tiles = 1024 tiles
    dim3 block(160);     // 4 consumer warps + 1 producer warp
    dynfilter_kernel<<<grid, block, SMEM_BYTES>>>(x, filt, out);
}